// round 6
// baseline (speedup 1.0000x reference)
#include <cuda_runtime.h>
#include <cstdint>

// Burden_29145648070955:  output = s_21 of the scalar map
//   s_{t+1} = (X.w + b) + 0.5*||w||^2 * nab(s_t),  nab(z)=0.5*(z+1)/sqrt((z+1)^2+1)
// One streaming matvec over X[65536,1024] + per-row scalar recurrence.
//
// R6: packed f32x2 FMA (sm_10x FFMA2, PTX-only) halves the FMA instruction
// stream; X/w consumed as ulonglong2 so each 64-bit half is a ready-packed
// f32x2 pair (zero repack cost). Traffic unchanged (LTS-cap bound at
// ~6.4 TB/s); goal is SM power/issue reduction -> clock headroom.

#define BATCH   65536
#define DIM     1024
#define DIMV    (DIM / 4)       // 256 x 16B per row
#define THREADS 128
#define ROWS_PER_WARP  32
#define ROWS_PER_BLOCK 128
#define GRID    (BATCH / ROWS_PER_BLOCK)   // 512
#define NITERS  21                          // 20 CCP steps + final apply

__device__ __forceinline__ uint64_t fma2(uint64_t a, uint64_t b, uint64_t c)
{
    uint64_t d;
    asm("fma.rn.f32x2 %0, %1, %2, %3;" : "=l"(d) : "l"(a), "l"(b), "l"(c));
    return d;
}

__device__ __forceinline__ float unpack_sum(uint64_t a, uint64_t b)
{
    float a0, a1, b0, b1;
    asm("mov.b64 {%0, %1}, %2;" : "=f"(a0), "=f"(a1) : "l"(a));
    asm("mov.b64 {%0, %1}, %2;" : "=f"(b0), "=f"(b1) : "l"(b));
    return (a0 + a1) + (b0 + b1);
}

// dot of one row fragment (8 x 16B) against w fragment: 16 FFMA2
__device__ __forceinline__ float dot8p(const ulonglong2* __restrict__ x,
                                       const ulonglong2* __restrict__ w)
{
    uint64_t acc0 = 0ull, acc1 = 0ull;   // packed (0.f, 0.f)
#pragma unroll
    for (int k = 0; k < 8; k++) {
        acc0 = fma2(x[k].x, w[k].x, acc0);
        acc1 = fma2(x[k].y, w[k].y, acc1);
    }
    return unpack_sum(acc0, acc1);
}

__global__ void __launch_bounds__(THREADS, 4)
burden_kernel(const float* __restrict__ X,
              const float* __restrict__ w,
              const float* __restrict__ b,
              float* __restrict__ out)
{
    const int lane    = threadIdx.x & 31;
    const int warp    = threadIdx.x >> 5;
    const int rowBase = blockIdx.x * ROWS_PER_BLOCK + warp * ROWS_PER_WARP;

    const ulonglong2* base = reinterpret_cast<const ulonglong2*>(X)
                           + (size_t)rowBase * DIMV;

    // ---- X loads FIRST: rows 0 and 1 in flight before any w work ----
    ulonglong2 A[8], B[8];
#pragma unroll
    for (int k = 0; k < 8; k++) A[k] = __ldcs(base + lane + 32 * k);
#pragma unroll
    for (int k = 0; k < 8; k++) B[k] = __ldcs(base + DIMV + lane + 32 * k);

    // ---- w fragment + ww reduction (overlapped with X flight) ----
    const ulonglong2* wvp = reinterpret_cast<const ulonglong2*>(w);
    ulonglong2 w4[8];
#pragma unroll
    for (int k = 0; k < 8; k++) w4[k] = wvp[lane + 32 * k];

    float wwp = dot8p(w4, w4);
#pragma unroll
    for (int o = 16; o > 0; o >>= 1) wwp += __shfl_xor_sync(0xffffffffu, wwp, o);
    const float ww = wwp;
    const float b0 = b[0];

    float myS = 0.f;   // lane j ends holding s0 for row rowBase + j

    // ---- steady state: rows j,j+1 resident; prefetch j+2,j+3 ----
#pragma unroll 1
    for (int j = 0; j < ROWS_PER_WARP - 2; j += 2) {
        float a0 = dot8p(A, w4);

        const ulonglong2* pA = base + (size_t)(j + 2) * DIMV;
#pragma unroll
        for (int k = 0; k < 8; k++) A[k] = __ldcs(pA + lane + 32 * k);

        float a1 = dot8p(B, w4);

        const ulonglong2* pB = base + (size_t)(j + 3) * DIMV;
#pragma unroll
        for (int k = 0; k < 8; k++) B[k] = __ldcs(pB + lane + 32 * k);

        // merged 2-row reduction: 6 shuffles
        a0 += __shfl_xor_sync(0xffffffffu, a0, 1);
        a1 += __shfl_xor_sync(0xffffffffu, a1, 1);
        float v = (lane & 1) ? a1 : a0;
#pragma unroll
        for (int o = 2; o <= 16; o <<= 1)
            v += __shfl_xor_sync(0xffffffffu, v, o);
        if ((lane & ~1) == j) myS = v;       // even lane: row j, odd: row j+1
    }

    // ---- peeled last pair (rows 30, 31) ----
    {
        const int j = ROWS_PER_WARP - 2;
        float a0 = dot8p(A, w4);
        float a1 = dot8p(B, w4);
        a0 += __shfl_xor_sync(0xffffffffu, a0, 1);
        a1 += __shfl_xor_sync(0xffffffffu, a1, 1);
        float v = (lane & 1) ? a1 : a0;
#pragma unroll
        for (int o = 2; o <= 16; o <<= 1)
            v += __shfl_xor_sync(0xffffffffu, v, o);
        if ((lane & ~1) == j) myS = v;
    }

    // ---- lane-parallel scalar CCP recurrence ----
    const float t0 = myS + b0;
    const float c  = 0.5f * ww;
    float s = t0;
#pragma unroll
    for (int it = 0; it < NITERS; it++) {
        float z   = s + 1.0f;                        // slope = 1
        float nab = 0.5f * z * rsqrtf(z * z + 1.0f);
        s = t0 + c * nab;
    }
    out[rowBase + lane] = s;   // coalesced 128B per warp
}

extern "C" void kernel_launch(void* const* d_in, const int* in_sizes, int n_in,
                              void* d_out, int out_size)
{
    const float* X = (const float*)d_in[0];
    const float* w = (const float*)d_in[1];
    const float* b = (const float*)d_in[2];
    float* out = (float*)d_out;
    (void)in_sizes; (void)n_in; (void)out_size;

    burden_kernel<<<GRID, THREADS>>>(X, w, b, out);
}

// round 7
// speedup vs baseline: 1.0059x; 1.0059x over previous
#include <cuda_runtime.h>
#include <cstdint>

// Burden_29145648070955  — FINAL (converged at memory-path ceiling)
//
// Reduction: the CCP fixed point only moves x along w, so
//   s_{t+1} = (X.w + b) + 0.5*||w||^2 * nab(s_t),  nab(z)=0.5*(z+1)*rsqrt((z+1)^2+1)
// and the output is exactly s_21. Kernel = one streaming matvec over
// X[65536,1024] (256 MB, single pass, no reuse) + per-row scalar recurrence.
//
// Measured across 6 variants: 6.1-6.4 TB/s plateau == achieved HBM/LTS
// ceiling (path-independent); 268 MB / ceiling ~= 43 us floor. This is the
// best-benched structure (R2) + packed f32x2 FMA (halved FMA stream).

#define BATCH   65536
#define DIM     1024
#define DIMV    (DIM / 4)       // 256 x 16B per row
#define THREADS 128
#define ROWS_PER_WARP  32
#define ROWS_PER_BLOCK 128
#define GRID    (BATCH / ROWS_PER_BLOCK)   // 512
#define NITERS  21                          // 20 CCP steps + final apply

__device__ __forceinline__ uint64_t fma2(uint64_t a, uint64_t b, uint64_t c)
{
    uint64_t d;
    asm("fma.rn.f32x2 %0, %1, %2, %3;" : "=l"(d) : "l"(a), "l"(b), "l"(c));
    return d;
}

__device__ __forceinline__ float unpack_sum(uint64_t a, uint64_t b)
{
    float a0, a1, b0, b1;
    asm("mov.b64 {%0, %1}, %2;" : "=f"(a0), "=f"(a1) : "l"(a));
    asm("mov.b64 {%0, %1}, %2;" : "=f"(b0), "=f"(b1) : "l"(b));
    return (a0 + a1) + (b0 + b1);
}

// dot of one row fragment (8 x 16B) against w fragment: 16 FFMA2
__device__ __forceinline__ float dot8p(const ulonglong2* __restrict__ x,
                                       const ulonglong2* __restrict__ w)
{
    uint64_t acc0 = 0ull, acc1 = 0ull;   // packed (0.f, 0.f)
#pragma unroll
    for (int k = 0; k < 8; k++) {
        acc0 = fma2(x[k].x, w[k].x, acc0);
        acc1 = fma2(x[k].y, w[k].y, acc1);
    }
    return unpack_sum(acc0, acc1);
}

__global__ void __launch_bounds__(THREADS, 4)
burden_kernel(const float* __restrict__ X,
              const float* __restrict__ w,
              const float* __restrict__ b,
              float* __restrict__ out)
{
    const int lane    = threadIdx.x & 31;
    const int warp    = threadIdx.x >> 5;
    const int rowBase = blockIdx.x * ROWS_PER_BLOCK + warp * ROWS_PER_WARP;

    // ---- w fragment in registers: lane owns 16B columns lane+32k ----
    const ulonglong2* wvp = reinterpret_cast<const ulonglong2*>(w);
    ulonglong2 w4[8];
#pragma unroll
    for (int k = 0; k < 8; k++) w4[k] = wvp[lane + 32 * k];

    // ---- ww = ||w||^2 (butterfly, all lanes) ----
    float wwp = dot8p(w4, w4);
#pragma unroll
    for (int o = 16; o > 0; o >>= 1) wwp += __shfl_xor_sync(0xffffffffu, wwp, o);
    const float ww = wwp;
    const float b0 = b[0];

    const ulonglong2* base = reinterpret_cast<const ulonglong2*>(X)
                           + (size_t)rowBase * DIMV;

    // ---- pipelined row dots: A/B double buffer ----
    ulonglong2 A[8], B[8];
#pragma unroll
    for (int k = 0; k < 8; k++) A[k] = __ldcs(base + lane + 32 * k);  // row 0

    float myS = 0.f;   // lane j ends holding s0 for row rowBase + j
#pragma unroll 1
    for (int j = 0; j < ROWS_PER_WARP; j += 2) {
        // prefetch row j+1 into B
        const ulonglong2* pB = base + (size_t)(j + 1) * DIMV;
#pragma unroll
        for (int k = 0; k < 8; k++) B[k] = __ldcs(pB + lane + 32 * k);

        float a0 = dot8p(A, w4);              // row j (A resident)

        // prefetch row j+2 into A (off on last iteration)
        if (j + 2 < ROWS_PER_WARP) {
            const ulonglong2* pA = base + (size_t)(j + 2) * DIMV;
#pragma unroll
            for (int k = 0; k < 8; k++) A[k] = __ldcs(pA + lane + 32 * k);
        }

        float a1 = dot8p(B, w4);              // row j+1

        // merged 2-row reduction: 6 shuffles
        a0 += __shfl_xor_sync(0xffffffffu, a0, 1);
        a1 += __shfl_xor_sync(0xffffffffu, a1, 1);
        float v = (lane & 1) ? a1 : a0;
#pragma unroll
        for (int o = 2; o <= 16; o <<= 1)
            v += __shfl_xor_sync(0xffffffffu, v, o);
        // even lanes hold sum(row j), odd lanes sum(row j+1)
        if ((lane & ~1) == j) myS = v;
    }

    // ---- lane-parallel scalar CCP recurrence ----
    const float t0 = myS + b0;
    const float c  = 0.5f * ww;
    float s = t0;
#pragma unroll
    for (int it = 0; it < NITERS; it++) {
        float z   = s + 1.0f;                        // slope = 1
        float nab = 0.5f * z * rsqrtf(z * z + 1.0f);
        s = t0 + c * nab;
    }
    out[rowBase + lane] = s;   // coalesced 128B per warp
}

extern "C" void kernel_launch(void* const* d_in, const int* in_sizes, int n_in,
                              void* d_out, int out_size)
{
    const float* X = (const float*)d_in[0];
    const float* w = (const float*)d_in[1];
    const float* b = (const float*)d_in[2];
    float* out = (float*)d_out;
    (void)in_sizes; (void)n_in; (void)out_size;

    burden_kernel<<<GRID, THREADS>>>(X, w, b, out);
}